// round 10
// baseline (speedup 1.0000x reference)
#include <cuda_runtime.h>
#include <math.h>

#define T_STEPS 512
#define BS      256
#define IC      128
#define HC      256
#define G4      1024   // 4*HC
#define NB      128    // persistent CTAs = 8 m-tiles x 16 n-groups (1/SM, co-resident)
#define NT      256    // threads per persistent CTA (2 warps per SMSP)

// ---------------- scratch (static device globals; no runtime allocation) ----------------
__device__ float g_gin [(size_t)T_STEPS * BS * G4];  // per-layer input projections (+biases)
__device__ float g_seq0[(size_t)T_STEPS * BS * HC];  // layer-0 output sequence
__device__ float g_h  [2][BS * HC];                  // h double-buffered by step parity
__device__ float g_ncb[2][BS * HC];                  // nc (for du dot) double-buffered
__device__ float g_du[BS];                           // carried across layers
__device__ int   g_skip[BS];                         // carried across layers
__device__ unsigned g_count;                         // grid barrier counter (monotonic)

// ---------------------------------------------------------------------------------------
// XLA-exact elementwise math (EmitFastTanh + LogisticExpander).
// ---------------------------------------------------------------------------------------
__device__ __forceinline__ float tanh_xla(float x)
{
    float ax = fabsf(x);
    float xc = fmaxf(-9.0f, fminf(x, 9.0f));
    float x2 = __fmul_rn(xc, xc);
    float p = -2.76076847742355e-16f;
    p = __fadd_rn(__fmul_rn(p, x2),  2.00018790482477e-13f);
    p = __fadd_rn(__fmul_rn(p, x2), -8.60467152213735e-11f);
    p = __fadd_rn(__fmul_rn(p, x2),  5.12229709037114e-08f);
    p = __fadd_rn(__fmul_rn(p, x2),  1.48572235717979e-05f);
    p = __fadd_rn(__fmul_rn(p, x2),  6.37261928875436e-04f);
    p = __fadd_rn(__fmul_rn(p, x2),  4.89352455891786e-03f);
    p = __fmul_rn(p, xc);
    float q =  1.19825839466702e-06f;
    q = __fadd_rn(__fmul_rn(q, x2),  1.18534705686654e-04f);
    q = __fadd_rn(__fmul_rn(q, x2),  2.26843463243900e-03f);
    q = __fadd_rn(__fmul_rn(q, x2),  4.89352518554385e-03f);
    float r = __fdiv_rn(p, q);
    return (ax < 0.0004f) ? x : r;
}

__device__ __forceinline__ float logi_xla(float x)
{
    float t = tanh_xla(__fmul_rn(0.5f, x));
    return __fadd_rn(0.5f, __fmul_rn(0.5f, t));
}

// Monotonic-counter grid barrier — proven formulation (volatile poll), with a short
// tight-spin phase before nanosleep backoff to cut wakeup latency.
__device__ __forceinline__ void grid_sync(unsigned& nbar)
{
    __syncthreads();
    if (threadIdx.x == 0) {
        __threadfence();
        nbar += 1;
        const unsigned target = nbar * NB;
        atomicAdd(&g_count, 1u);
        int s = 0;
        while (*(volatile unsigned*)&g_count < target) {
            if (++s > 64) __nanosleep(64);
        }
    }
    __syncthreads();
}

// ---------------------------------------------------------------------------------------
// Input projection (unchanged — passed). Ascending-k single-accumulator FMA chains.
// ---------------------------------------------------------------------------------------
__global__ __launch_bounds__(256) void inproj_kernel(
    const float* __restrict__ xin, int useSeq0, int K,
    const float* __restrict__ Wih,
    const float* __restrict__ b0, const float* __restrict__ b1)
{
    const float* A = useSeq0 ? g_seq0 : xin;
    __shared__ float As[8][132];
    __shared__ float Bs[8][132];

    const int tid = threadIdx.x;
    const int n0  = blockIdx.x << 7;
    const int m0  = blockIdx.y << 7;
    const int ty  = tid >> 4;
    const int tx  = tid & 15;
    const int r   = tid >> 1;
    const int kc  = (tid & 1) << 2;

    const float* Ap = A   + (size_t)(m0 + r) * K + kc;
    const float* Wp = Wih + (size_t)(n0 + r) * K + kc;

    float acc[8][8] = {};
    const int nch = K >> 3;
    float4 pa = __ldg((const float4*)Ap);
    float4 pw = __ldg((const float4*)Wp);

    for (int ch = 0; ch < nch; ch++) {
        As[kc + 0][r] = pa.x; As[kc + 1][r] = pa.y; As[kc + 2][r] = pa.z; As[kc + 3][r] = pa.w;
        Bs[kc + 0][r] = pw.x; Bs[kc + 1][r] = pw.y; Bs[kc + 2][r] = pw.z; Bs[kc + 3][r] = pw.w;
        __syncthreads();
        if (ch + 1 < nch) {
            pa = __ldg((const float4*)(Ap + (ch + 1) * 8));
            pw = __ldg((const float4*)(Wp + (ch + 1) * 8));
        }
#pragma unroll
        for (int k = 0; k < 8; k++) {
            float4 a0 = *(const float4*)&As[k][ty << 3];
            float4 a1 = *(const float4*)&As[k][(ty << 3) + 4];
            float4 w0 = *(const float4*)&Bs[k][tx << 3];
            float4 w1 = *(const float4*)&Bs[k][(tx << 3) + 4];
            float ar[8] = {a0.x, a0.y, a0.z, a0.w, a1.x, a1.y, a1.z, a1.w};
            float br[8] = {w0.x, w0.y, w0.z, w0.w, w1.x, w1.y, w1.z, w1.w};
#pragma unroll
            for (int i = 0; i < 8; i++)
#pragma unroll
                for (int j = 0; j < 8; j++)
                    acc[i][j] = fmaf(ar[i], br[j], acc[i][j]);
        }
        __syncthreads();
    }

    const int col = n0 + (tx << 3);
    float bias[8];
#pragma unroll
    for (int j = 0; j < 8; j++) bias[j] = __fadd_rn(b0[col + j], b1[col + j]);
#pragma unroll
    for (int i = 0; i < 8; i++) {
        size_t row = (size_t)m0 + (ty << 3) + i;
        float* o = g_gin + row * G4 + col;
#pragma unroll
        for (int j = 0; j < 8; j++) o[j] = __fadd_rn(acc[i][j], bias[j]);
    }
}

// ---------------------------------------------------------------------------------------
// du-dot + state update (warps 0-3 only; 4 threads/row, exact Eigen 4-chain order).
// ---------------------------------------------------------------------------------------
__device__ __forceinline__ void dot_update(
    int parity, int m0, int b, int q4, const float* slw, float lb0v,
    float* su, float* sdu, int* sskip)
{
    const float* nrow = g_ncb[parity] + (size_t)(m0 + b) * HC;
    float a = 0.0f;
    for (int k = q4; k < HC; k += 4)
        a = fmaf(__ldcg(nrow + k), slw[k], a);
    float v1  = __fadd_rn(a,  __shfl_xor_sync(0xffffffffu, a, 1));
    float dot = __fadd_rn(v1, __shfl_xor_sync(0xffffffffu, v1, 2));
    if (q4 == 0) {
        const float uo  = su[b];
        const float duo = sdu[b];
        const int   m   = sskip[b];
        const float bu  = rintf(uo);                       // jnp.round (half-to-even)
        const float omb = __fsub_rn(1.0f, bu);
        float nu, ndu;
        if (!m) {
            float dn = logi_xla(__fadd_rn(dot, lb0v));
            nu = __fmul_rn(dn, bu); ndu = dn;
        } else {
            nu = __fmul_rn(fminf(fmaxf(__fadd_rn(uo, duo), 0.0f), 1.0f), omb);
            ndu = duo;
        }
        su[b] = nu; sdu[b] = ndu;
        sskip[b] = ((__fsub_rn(ceilf(__fdiv_rn(0.5f, nu)), 1.0f)) > 0.0f) ? 1 : 0;
    }
}

// ---------------------------------------------------------------------------------------
// Fused persistent per-layer kernel, NT=256 (2 warps/SMSP for latency hiding).
// CTA = (m-tile of 32 rows) x (n-group of 16 h-cols, all 4 gates). Thread tile 2x4.
// ---------------------------------------------------------------------------------------
#define WS_ELEMS (256 * 68)
#define HS_ELEMS (256 * 36)
#define DYN_SMEM ((WS_ELEMS + HS_ELEMS) * 4)

__global__ __launch_bounds__(NT, 1) void layer_kernel(
    const float* __restrict__ W,                   // Whh [1024][256]
    const float* __restrict__ lw, const float* __restrict__ lb,
    float* __restrict__ seq_out, int to_seq0,
    float* __restrict__ outH, float* __restrict__ outC)
{
    extern __shared__ float sm[];
    float* Ws = sm;               // [k][64 local gate-cols] pad 68
    float* Hs = sm + WS_ELEMS;    // [k][32 rows] pad 36
    __shared__ float sgates[32 * 68];
    __shared__ float cloc[32 * 16];
    __shared__ float hloc[32 * 16];
    __shared__ float slw[256];
    __shared__ float su[32], sdu[32];
    __shared__ int   sskip[32];

    const int tid   = threadIdx.x;
    const int bid   = blockIdx.x;
    const int ng    = bid & 15;          // n-group: h-cols [16ng, 16ng+16)
    const int m0    = (bid >> 4) * 32;   // m-tile rows
    const int jbase = ng << 4;
    const int tx    = tid & 15;          // GEMM: 4 local gate-cols (tx*4..+3)
    const int ty    = tid >> 4;          // GEMM: 2 rows (2ty, 2ty+1)
    const int wid   = tid >> 5;
    const int lane  = tid & 31;
    const int pr    = tid >> 3;          // pointwise row 0..31
    const int pc    = (tid & 7) << 1;    // pointwise 2 cols (pc, pc+1) of 16

    // lw + Whh slab (64 gate-cols x 256 k) cached in SMEM, transposed to [k][c]
    slw[tid] = lw[tid];
    const float lb0v = lb[0];
    for (int i = tid; i < 64 * 64; i += NT) {
        int c  = i >> 6;                              // local gate-col 0..63
        int k4 = (i & 63) << 2;
        int grow = (c >> 4) * HC + jbase + (c & 15);  // Whh row (global gate col)
        float4 v = __ldcg((const float4*)(W + (size_t)grow * HC + k4));
        Ws[(k4 + 0) * 68 + c] = v.x; Ws[(k4 + 1) * 68 + c] = v.y;
        Ws[(k4 + 2) * 68 + c] = v.z; Ws[(k4 + 3) * 68 + c] = v.w;
    }

    if (tid < 32) {
        su[tid]    = 1.0f;
        sdu[tid]   = g_du[m0 + tid];
        sskip[tid] = g_skip[m0 + tid];
    }
    for (int i = tid; i < 32 * 16; i += NT) { cloc[i] = 0.0f; hloc[i] = 0.0f; }
    __syncthreads();

    unsigned nbar = 0;

    for (int t = 0; t < T_STEPS; t++) {
        // gin prefetch: this thread's 2x4 gate patch (static data)
        float4 pg[2];
        {
            const int gate = tx >> 2;
            const int gj0  = (tx & 3) << 2;
            const float* gp = g_gin + ((size_t)t * BS + m0 + (ty << 1)) * G4
                              + gate * HC + jbase + gj0;
            pg[0] = __ldcg((const float4*)gp);
            pg[1] = __ldcg((const float4*)(gp + G4));
        }

        // Hs load: h(t) from parity buffer t&1 -> [k][m]
        {
            const float* hsrc = g_h[t & 1];
            for (int i = tid; i < 32 * 64; i += NT) {
                int rr = i >> 6;
                int k4 = (i & 63) << 2;
                float4 v = __ldcg((const float4*)(hsrc + (size_t)(m0 + rr) * HC + k4));
                Hs[(k4 + 0) * 36 + rr] = v.x; Hs[(k4 + 1) * 36 + rr] = v.y;
                Hs[(k4 + 2) * 36 + rr] = v.z; Hs[(k4 + 3) * 36 + rr] = v.w;
            }
        }

        // state update from previous step's nc (warps 0-3)
        if (t > 0 && tid < 128) dot_update((t - 1) & 1, m0, tid >> 2, tid & 3,
                                           slw, lb0v, su, sdu, sskip);
        __syncthreads();

        // GEMM: 32 rows x 64 local gate-cols -> sgates (+gin). Warp rows: 4*wid..+3.
        {
            int fl = (lane < 4) ? sskip[(wid << 2) + lane] : 1;
            const bool allskip = __all_sync(0xffffffffu, fl != 0);
            if (!allskip) {
                float acc[2][4] = {};
                const float* hp = &Hs[ty << 1];
                const float* wp = &Ws[tx << 2];
#pragma unroll 8
                for (int k = 0; k < HC; k++) {       // strictly ascending k
                    float2 a = *(const float2*)(hp + k * 36);
                    float4 b = *(const float4*)(wp + k * 68);
                    acc[0][0] = fmaf(a.x, b.x, acc[0][0]); acc[0][1] = fmaf(a.x, b.y, acc[0][1]);
                    acc[0][2] = fmaf(a.x, b.z, acc[0][2]); acc[0][3] = fmaf(a.x, b.w, acc[0][3]);
                    acc[1][0] = fmaf(a.y, b.x, acc[1][0]); acc[1][1] = fmaf(a.y, b.y, acc[1][1]);
                    acc[1][2] = fmaf(a.y, b.z, acc[1][2]); acc[1][3] = fmaf(a.y, b.w, acc[1][3]);
                }
#pragma unroll
                for (int i = 0; i < 2; i++) {
                    float4 v = make_float4(__fadd_rn(acc[i][0], pg[i].x),
                                           __fadd_rn(acc[i][1], pg[i].y),
                                           __fadd_rn(acc[i][2], pg[i].z),
                                           __fadd_rn(acc[i][3], pg[i].w));
                    *(float4*)&sgates[((ty << 1) + i) * 68 + (tx << 2)] = v;
                }
            }
        }
        __syncthreads();

        // pointwise: 1 row x 2 cols per thread, all CTA-local
        {
            const float uo  = su[pr];
            const int   m   = sskip[pr];
            const float bu  = rintf(uo);
            const float omb = __fsub_rn(1.0f, bu);
            float* cl = cloc + pr * 16 + pc;
            float* hl = hloc + pr * 16 + pc;
            float nh[2], nc[2];
            if (!m) {
                const float* sg = sgates + pr * 68;
#pragma unroll
                for (int s = 0; s < 2; s++) {
                    int jl = pc + s;
                    float gi = sg[jl], gf = sg[16 + jl], gg = sg[32 + jl], go = sg[48 + jl];
                    float cc = __fadd_rn(__fmul_rn(logi_xla(gf), cl[s]),
                                         __fmul_rn(logi_xla(gi), tanh_xla(gg)));
                    float ch = __fmul_rn(logi_xla(go), tanh_xla(cc));
                    nc[s] = __fmul_rn(cc, bu);
                    nh[s] = __fmul_rn(ch, bu);
                }
            } else {
#pragma unroll
                for (int s = 0; s < 2; s++) {
                    nh[s] = __fmul_rn(hl[s], omb);
                    nc[s] = __fmul_rn(cl[s], omb);
                }
            }
            cl[0] = nc[0]; cl[1] = nc[1];
            hl[0] = nh[0]; hl[1] = nh[1];

            const size_t roff = (size_t)(m0 + pr) * HC + jbase + pc;
            float2 nh2 = make_float2(nh[0], nh[1]);
            __stcg((float2*)(g_h[(t + 1) & 1] + roff), nh2);      // next-step h buffer
            if (!m) {
                __stcg((float2*)(g_ncb[t & 1] + roff), make_float2(nc[0], nc[1]));
            }
            float* dp = (to_seq0 ? g_seq0 : seq_out) + (size_t)t * BS * HC + roff;
            __stcg((float2*)dp, nh2);
        }

        grid_sync(nbar);
    }

    // final state update -> carried du/skip + h/c outputs
    if (tid < 128) dot_update((T_STEPS - 1) & 1, m0, tid >> 2, tid & 3,
                              slw, lb0v, su, sdu, sskip);
    __syncthreads();
    if (ng == 0 && tid < 32) {
        g_du[m0 + tid]   = sdu[tid];
        g_skip[m0 + tid] = sskip[tid];
    }
    {
        const size_t roff = (size_t)(m0 + pr) * HC + jbase + pc;
        *(float2*)(outH + roff) = *(float2*)(hloc + pr * 16 + pc);
        *(float2*)(outC + roff) = *(float2*)(cloc + pr * 16 + pc);
    }
}

// ---------------------------------------------------------------------------------------
__global__ void init0_kernel()   // before layer 0: full reset
{
    int i = blockIdx.x * blockDim.x + threadIdx.x;
    if (i < BS * HC) g_h[0][i] = 0.0f;
    if (i < BS)      { g_du[i] = 0.0f; g_skip[i] = 0; }
    if (i == 0)      g_count = 0u;
}

__global__ void init1_kernel()   // before layer 1: keep carried du/skip
{
    int i = blockIdx.x * blockDim.x + threadIdx.x;
    if (i < BS * HC) g_h[0][i] = 0.0f;
    if (i == 0)      g_count = 0u;
}

// ---------------------------------------------------------------------------------------
extern "C" void kernel_launch(void* const* d_in, const int* in_sizes, int n_in,
                              void* d_out, int out_size)
{
    const float* x    = (const float*)d_in[0];
    const float* Wih0 = (const float*)d_in[1];
    const float* Whh0 = (const float*)d_in[2];
    const float* bih0 = (const float*)d_in[3];
    const float* bhh0 = (const float*)d_in[4];
    const float* lw0  = (const float*)d_in[5];
    const float* lb0  = (const float*)d_in[6];
    const float* Wih1 = (const float*)d_in[7];
    const float* Whh1 = (const float*)d_in[8];
    const float* bih1 = (const float*)d_in[9];
    const float* bhh1 = (const float*)d_in[10];
    const float* lw1  = (const float*)d_in[11];
    const float* lb1  = (const float*)d_in[12];

    float* out   = (float*)d_out;                         // [T, BS, HC]
    float* outHs = out + (size_t)T_STEPS * BS * HC;       // [2, BS, HC]
    float* outCs = outHs + 2 * BS * HC;                   // [2, BS, HC]

    cudaFuncSetAttribute(layer_kernel, cudaFuncAttributeMaxDynamicSharedMemorySize, DYN_SMEM);

    dim3 proj_grid(G4 / 128, (T_STEPS * BS) / 128);       // (8, 1024)

    // launch order keeps layer_kernel as launch #6 (ncu -s 5 -c 1 captures it)
    inproj_kernel<<<proj_grid, 256>>>(x, 0, IC, Wih0, bih0, bhh0);          // 1
    init0_kernel<<<256, 256>>>();                                           // 2
    layer_kernel<<<NB, NT, DYN_SMEM>>>(Whh0, lw0, lb0, nullptr, 1,          // 3
                                       outHs, outCs);
    inproj_kernel<<<proj_grid, 256>>>(nullptr, 1, HC, Wih1, bih1, bhh1);    // 4
    init1_kernel<<<256, 256>>>();                                           // 5
    layer_kernel<<<NB, NT, DYN_SMEM>>>(Whh1, lw1, lb1, out, 0,              // 6
                                       outHs + BS * HC, outCs + BS * HC);
}

// round 11
// speedup vs baseline: 1.0012x; 1.0012x over previous
#include <cuda_runtime.h>
#include <math.h>

#define T_STEPS 512
#define BS      256
#define IC      128
#define HC      256
#define G4      1024   // 4*HC
#define NB      128    // persistent CTAs = 8 m-tiles x 16 n-groups (1/SM, co-resident)
#define NT      256    // threads per persistent CTA (2 warps per SMSP)

// ---------------- scratch (static device globals; no runtime allocation) ----------------
__device__ float g_gin [(size_t)T_STEPS * BS * G4];  // per-layer input projections (+biases)
__device__ float g_seq0[(size_t)T_STEPS * BS * HC];  // layer-0 output sequence
__device__ float g_h  [2][BS * HC];                  // h double-buffered by step parity
__device__ float g_ncb[2][BS * HC];                  // nc (for du dot) double-buffered
__device__ float g_du[BS];                           // carried across layers
__device__ int   g_skip[BS];                         // carried across layers
__device__ unsigned g_count;                         // grid barrier counter (monotonic)

// ---------------------------------------------------------------------------------------
// XLA-exact elementwise math (EmitFastTanh + LogisticExpander).
// ---------------------------------------------------------------------------------------
__device__ __forceinline__ float tanh_xla(float x)
{
    float ax = fabsf(x);
    float xc = fmaxf(-9.0f, fminf(x, 9.0f));
    float x2 = __fmul_rn(xc, xc);
    float p = -2.76076847742355e-16f;
    p = __fadd_rn(__fmul_rn(p, x2),  2.00018790482477e-13f);
    p = __fadd_rn(__fmul_rn(p, x2), -8.60467152213735e-11f);
    p = __fadd_rn(__fmul_rn(p, x2),  5.12229709037114e-08f);
    p = __fadd_rn(__fmul_rn(p, x2),  1.48572235717979e-05f);
    p = __fadd_rn(__fmul_rn(p, x2),  6.37261928875436e-04f);
    p = __fadd_rn(__fmul_rn(p, x2),  4.89352455891786e-03f);
    p = __fmul_rn(p, xc);
    float q =  1.19825839466702e-06f;
    q = __fadd_rn(__fmul_rn(q, x2),  1.18534705686654e-04f);
    q = __fadd_rn(__fmul_rn(q, x2),  2.26843463243900e-03f);
    q = __fadd_rn(__fmul_rn(q, x2),  4.89352518554385e-03f);
    float r = __fdiv_rn(p, q);
    return (ax < 0.0004f) ? x : r;
}

__device__ __forceinline__ float logi_xla(float x)
{
    float t = tanh_xla(__fmul_rn(0.5f, x));
    return __fadd_rn(0.5f, __fmul_rn(0.5f, t));
}

// Monotonic-counter grid barrier — proven formulation (volatile poll), with a short
// tight-spin phase before nanosleep backoff to cut wakeup latency.
__device__ __forceinline__ void grid_sync(unsigned& nbar)
{
    __syncthreads();
    if (threadIdx.x == 0) {
        __threadfence();
        nbar += 1;
        const unsigned target = nbar * NB;
        atomicAdd(&g_count, 1u);
        int s = 0;
        while (*(volatile unsigned*)&g_count < target) {
            if (++s > 64) __nanosleep(64);
        }
    }
    __syncthreads();
}

// ---------------------------------------------------------------------------------------
// Input projection (unchanged — passed). Ascending-k single-accumulator FMA chains.
// ---------------------------------------------------------------------------------------
__global__ __launch_bounds__(256) void inproj_kernel(
    const float* __restrict__ xin, int useSeq0, int K,
    const float* __restrict__ Wih,
    const float* __restrict__ b0, const float* __restrict__ b1)
{
    const float* A = useSeq0 ? g_seq0 : xin;
    __shared__ float As[8][132];
    __shared__ float Bs[8][132];

    const int tid = threadIdx.x;
    const int n0  = blockIdx.x << 7;
    const int m0  = blockIdx.y << 7;
    const int ty  = tid >> 4;
    const int tx  = tid & 15;
    const int r   = tid >> 1;
    const int kc  = (tid & 1) << 2;

    const float* Ap = A   + (size_t)(m0 + r) * K + kc;
    const float* Wp = Wih + (size_t)(n0 + r) * K + kc;

    float acc[8][8] = {};
    const int nch = K >> 3;
    float4 pa = __ldg((const float4*)Ap);
    float4 pw = __ldg((const float4*)Wp);

    for (int ch = 0; ch < nch; ch++) {
        As[kc + 0][r] = pa.x; As[kc + 1][r] = pa.y; As[kc + 2][r] = pa.z; As[kc + 3][r] = pa.w;
        Bs[kc + 0][r] = pw.x; Bs[kc + 1][r] = pw.y; Bs[kc + 2][r] = pw.z; Bs[kc + 3][r] = pw.w;
        __syncthreads();
        if (ch + 1 < nch) {
            pa = __ldg((const float4*)(Ap + (ch + 1) * 8));
            pw = __ldg((const float4*)(Wp + (ch + 1) * 8));
        }
#pragma unroll
        for (int k = 0; k < 8; k++) {
            float4 a0 = *(const float4*)&As[k][ty << 3];
            float4 a1 = *(const float4*)&As[k][(ty << 3) + 4];
            float4 w0 = *(const float4*)&Bs[k][tx << 3];
            float4 w1 = *(const float4*)&Bs[k][(tx << 3) + 4];
            float ar[8] = {a0.x, a0.y, a0.z, a0.w, a1.x, a1.y, a1.z, a1.w};
            float br[8] = {w0.x, w0.y, w0.z, w0.w, w1.x, w1.y, w1.z, w1.w};
#pragma unroll
            for (int i = 0; i < 8; i++)
#pragma unroll
                for (int j = 0; j < 8; j++)
                    acc[i][j] = fmaf(ar[i], br[j], acc[i][j]);
        }
        __syncthreads();
    }

    const int col = n0 + (tx << 3);
    float bias[8];
#pragma unroll
    for (int j = 0; j < 8; j++) bias[j] = __fadd_rn(b0[col + j], b1[col + j]);
#pragma unroll
    for (int i = 0; i < 8; i++) {
        size_t row = (size_t)m0 + (ty << 3) + i;
        float* o = g_gin + row * G4 + col;
#pragma unroll
        for (int j = 0; j < 8; j++) o[j] = __fadd_rn(acc[i][j], bias[j]);
    }
}

// ---------------------------------------------------------------------------------------
// du-dot + state update (warps 0-3 only; 4 threads/row, exact Eigen 4-chain order).
// ---------------------------------------------------------------------------------------
__device__ __forceinline__ void dot_update(
    int parity, int m0, int b, int q4, const float* slw, float lb0v,
    float* su, float* sdu, int* sskip)
{
    const float* nrow = g_ncb[parity] + (size_t)(m0 + b) * HC;
    float a = 0.0f;
    for (int k = q4; k < HC; k += 4)
        a = fmaf(__ldcg(nrow + k), slw[k], a);
    float v1  = __fadd_rn(a,  __shfl_xor_sync(0xffffffffu, a, 1));
    float dot = __fadd_rn(v1, __shfl_xor_sync(0xffffffffu, v1, 2));
    if (q4 == 0) {
        const float uo  = su[b];
        const float duo = sdu[b];
        const int   m   = sskip[b];
        const float bu  = rintf(uo);                       // jnp.round (half-to-even)
        const float omb = __fsub_rn(1.0f, bu);
        float nu, ndu;
        if (!m) {
            float dn = logi_xla(__fadd_rn(dot, lb0v));
            nu = __fmul_rn(dn, bu); ndu = dn;
        } else {
            nu = __fmul_rn(fminf(fmaxf(__fadd_rn(uo, duo), 0.0f), 1.0f), omb);
            ndu = duo;
        }
        su[b] = nu; sdu[b] = ndu;
        sskip[b] = ((__fsub_rn(ceilf(__fdiv_rn(0.5f, nu)), 1.0f)) > 0.0f) ? 1 : 0;
    }
}

// ---------------------------------------------------------------------------------------
// Fused persistent per-layer kernel, NT=256 (2 warps/SMSP for latency hiding).
// CTA = (m-tile of 32 rows) x (n-group of 16 h-cols, all 4 gates). Thread tile 2x4.
// ---------------------------------------------------------------------------------------
#define WS_ELEMS (256 * 68)
#define HS_ELEMS (256 * 36)
#define DYN_SMEM ((WS_ELEMS + HS_ELEMS) * 4)

__global__ __launch_bounds__(NT, 1) void layer_kernel(
    const float* __restrict__ W,                   // Whh [1024][256]
    const float* __restrict__ lw, const float* __restrict__ lb,
    float* __restrict__ seq_out, int to_seq0,
    float* __restrict__ outH, float* __restrict__ outC)
{
    extern __shared__ float sm[];
    float* Ws = sm;               // [k][64 local gate-cols] pad 68
    float* Hs = sm + WS_ELEMS;    // [k][32 rows] pad 36
    __shared__ float sgates[32 * 68];
    __shared__ float cloc[32 * 16];
    __shared__ float hloc[32 * 16];
    __shared__ float slw[256];
    __shared__ float su[32], sdu[32];
    __shared__ int   sskip[32];

    const int tid   = threadIdx.x;
    const int bid   = blockIdx.x;
    const int ng    = bid & 15;          // n-group: h-cols [16ng, 16ng+16)
    const int m0    = (bid >> 4) * 32;   // m-tile rows
    const int jbase = ng << 4;
    const int tx    = tid & 15;          // GEMM: 4 local gate-cols (tx*4..+3)
    const int ty    = tid >> 4;          // GEMM: 2 rows (2ty, 2ty+1)
    const int wid   = tid >> 5;
    const int lane  = tid & 31;
    const int pr    = tid >> 3;          // pointwise row 0..31
    const int pc    = (tid & 7) << 1;    // pointwise 2 cols (pc, pc+1) of 16

    // lw + Whh slab (64 gate-cols x 256 k) cached in SMEM, transposed to [k][c]
    slw[tid] = lw[tid];
    const float lb0v = lb[0];
    for (int i = tid; i < 64 * 64; i += NT) {
        int c  = i >> 6;                              // local gate-col 0..63
        int k4 = (i & 63) << 2;
        int grow = (c >> 4) * HC + jbase + (c & 15);  // Whh row (global gate col)
        float4 v = __ldcg((const float4*)(W + (size_t)grow * HC + k4));
        Ws[(k4 + 0) * 68 + c] = v.x; Ws[(k4 + 1) * 68 + c] = v.y;
        Ws[(k4 + 2) * 68 + c] = v.z; Ws[(k4 + 3) * 68 + c] = v.w;
    }

    if (tid < 32) {
        su[tid]    = 1.0f;
        sdu[tid]   = g_du[m0 + tid];
        sskip[tid] = g_skip[m0 + tid];
    }
    for (int i = tid; i < 32 * 16; i += NT) { cloc[i] = 0.0f; hloc[i] = 0.0f; }
    __syncthreads();

    unsigned nbar = 0;

    for (int t = 0; t < T_STEPS; t++) {
        // gin prefetch: this thread's 2x4 gate patch (static data)
        float4 pg[2];
        {
            const int gate = tx >> 2;
            const int gj0  = (tx & 3) << 2;
            const float* gp = g_gin + ((size_t)t * BS + m0 + (ty << 1)) * G4
                              + gate * HC + jbase + gj0;
            pg[0] = __ldcg((const float4*)gp);
            pg[1] = __ldcg((const float4*)(gp + G4));
        }

        // Hs load: h(t) from parity buffer t&1 -> [k][m]
        {
            const float* hsrc = g_h[t & 1];
            for (int i = tid; i < 32 * 64; i += NT) {
                int rr = i >> 6;
                int k4 = (i & 63) << 2;
                float4 v = __ldcg((const float4*)(hsrc + (size_t)(m0 + rr) * HC + k4));
                Hs[(k4 + 0) * 36 + rr] = v.x; Hs[(k4 + 1) * 36 + rr] = v.y;
                Hs[(k4 + 2) * 36 + rr] = v.z; Hs[(k4 + 3) * 36 + rr] = v.w;
            }
        }

        // state update from previous step's nc (warps 0-3)
        if (t > 0 && tid < 128) dot_update((t - 1) & 1, m0, tid >> 2, tid & 3,
                                           slw, lb0v, su, sdu, sskip);
        __syncthreads();

        // GEMM: 32 rows x 64 local gate-cols -> sgates (+gin). Warp rows: 4*wid..+3.
        {
            int fl = (lane < 4) ? sskip[(wid << 2) + lane] : 1;
            const bool allskip = __all_sync(0xffffffffu, fl != 0);
            if (!allskip) {
                float acc[2][4] = {};
                const float* hp = &Hs[ty << 1];
                const float* wp = &Ws[tx << 2];
#pragma unroll 8
                for (int k = 0; k < HC; k++) {       // strictly ascending k
                    float2 a = *(const float2*)(hp + k * 36);
                    float4 b = *(const float4*)(wp + k * 68);
                    acc[0][0] = fmaf(a.x, b.x, acc[0][0]); acc[0][1] = fmaf(a.x, b.y, acc[0][1]);
                    acc[0][2] = fmaf(a.x, b.z, acc[0][2]); acc[0][3] = fmaf(a.x, b.w, acc[0][3]);
                    acc[1][0] = fmaf(a.y, b.x, acc[1][0]); acc[1][1] = fmaf(a.y, b.y, acc[1][1]);
                    acc[1][2] = fmaf(a.y, b.z, acc[1][2]); acc[1][3] = fmaf(a.y, b.w, acc[1][3]);
                }
#pragma unroll
                for (int i = 0; i < 2; i++) {
                    float4 v = make_float4(__fadd_rn(acc[i][0], pg[i].x),
                                           __fadd_rn(acc[i][1], pg[i].y),
                                           __fadd_rn(acc[i][2], pg[i].z),
                                           __fadd_rn(acc[i][3], pg[i].w));
                    *(float4*)&sgates[((ty << 1) + i) * 68 + (tx << 2)] = v;
                }
            }
        }
        __syncthreads();

        // pointwise: 1 row x 2 cols per thread, all CTA-local
        {
            const float uo  = su[pr];
            const int   m   = sskip[pr];
            const float bu  = rintf(uo);
            const float omb = __fsub_rn(1.0f, bu);
            float* cl = cloc + pr * 16 + pc;
            float* hl = hloc + pr * 16 + pc;
            float nh[2], nc[2];
            if (!m) {
                const float* sg = sgates + pr * 68;
#pragma unroll
                for (int s = 0; s < 2; s++) {
                    int jl = pc + s;
                    float gi = sg[jl], gf = sg[16 + jl], gg = sg[32 + jl], go = sg[48 + jl];
                    float cc = __fadd_rn(__fmul_rn(logi_xla(gf), cl[s]),
                                         __fmul_rn(logi_xla(gi), tanh_xla(gg)));
                    float ch = __fmul_rn(logi_xla(go), tanh_xla(cc));
                    nc[s] = __fmul_rn(cc, bu);
                    nh[s] = __fmul_rn(ch, bu);
                }
            } else {
#pragma unroll
                for (int s = 0; s < 2; s++) {
                    nh[s] = __fmul_rn(hl[s], omb);
                    nc[s] = __fmul_rn(cl[s], omb);
                }
            }
            cl[0] = nc[0]; cl[1] = nc[1];
            hl[0] = nh[0]; hl[1] = nh[1];

            const size_t roff = (size_t)(m0 + pr) * HC + jbase + pc;
            float2 nh2 = make_float2(nh[0], nh[1]);
            __stcg((float2*)(g_h[(t + 1) & 1] + roff), nh2);      // next-step h buffer
            if (!m) {
                __stcg((float2*)(g_ncb[t & 1] + roff), make_float2(nc[0], nc[1]));
            }
            float* dp = (to_seq0 ? g_seq0 : seq_out) + (size_t)t * BS * HC + roff;
            __stcg((float2*)dp, nh2);
        }

        grid_sync(nbar);
    }

    // final state update -> carried du/skip + h/c outputs
    if (tid < 128) dot_update((T_STEPS - 1) & 1, m0, tid >> 2, tid & 3,
                              slw, lb0v, su, sdu, sskip);
    __syncthreads();
    if (ng == 0 && tid < 32) {
        g_du[m0 + tid]   = sdu[tid];
        g_skip[m0 + tid] = sskip[tid];
    }
    {
        const size_t roff = (size_t)(m0 + pr) * HC + jbase + pc;
        *(float2*)(outH + roff) = *(float2*)(hloc + pr * 16 + pc);
        *(float2*)(outC + roff) = *(float2*)(cloc + pr * 16 + pc);
    }
}

// ---------------------------------------------------------------------------------------
__global__ void init0_kernel()   // before layer 0: full reset
{
    int i = blockIdx.x * blockDim.x + threadIdx.x;
    if (i < BS * HC) g_h[0][i] = 0.0f;
    if (i < BS)      { g_du[i] = 0.0f; g_skip[i] = 0; }
    if (i == 0)      g_count = 0u;
}

__global__ void init1_kernel()   // before layer 1: keep carried du/skip
{
    int i = blockIdx.x * blockDim.x + threadIdx.x;
    if (i < BS * HC) g_h[0][i] = 0.0f;
    if (i == 0)      g_count = 0u;
}

// ---------------------------------------------------------------------------------------
extern "C" void kernel_launch(void* const* d_in, const int* in_sizes, int n_in,
                              void* d_out, int out_size)
{
    const float* x    = (const float*)d_in[0];
    const float* Wih0 = (const float*)d_in[1];
    const float* Whh0 = (const float*)d_in[2];
    const float* bih0 = (const float*)d_in[3];
    const float* bhh0 = (const float*)d_in[4];
    const float* lw0  = (const float*)d_in[5];
    const float* lb0  = (const float*)d_in[6];
    const float* Wih1 = (const float*)d_in[7];
    const float* Whh1 = (const float*)d_in[8];
    const float* bih1 = (const float*)d_in[9];
    const float* bhh1 = (const float*)d_in[10];
    const float* lw1  = (const float*)d_in[11];
    const float* lb1  = (const float*)d_in[12];

    float* out   = (float*)d_out;                         // [T, BS, HC]
    float* outHs = out + (size_t)T_STEPS * BS * HC;       // [2, BS, HC]
    float* outCs = outHs + 2 * BS * HC;                   // [2, BS, HC]

    cudaFuncSetAttribute(layer_kernel, cudaFuncAttributeMaxDynamicSharedMemorySize, DYN_SMEM);

    dim3 proj_grid(G4 / 128, (T_STEPS * BS) / 128);       // (8, 1024)

    // launch order keeps layer_kernel as launch #6 (ncu -s 5 -c 1 captures it)
    inproj_kernel<<<proj_grid, 256>>>(x, 0, IC, Wih0, bih0, bhh0);          // 1
    init0_kernel<<<256, 256>>>();                                           // 2
    layer_kernel<<<NB, NT, DYN_SMEM>>>(Whh0, lw0, lb0, nullptr, 1,          // 3
                                       outHs, outCs);
    inproj_kernel<<<proj_grid, 256>>>(nullptr, 1, HC, Wih1, bih1, bhh1);    // 4
    init1_kernel<<<256, 256>>>();                                           // 5
    layer_kernel<<<NB, NT, DYN_SMEM>>>(Whh1, lw1, lb1, out, 0,              // 6
                                       outHs + BS * HC, outCs + BS * HC);
}

// round 12
// speedup vs baseline: 1.0028x; 1.0016x over previous
#include <cuda_runtime.h>
#include <math.h>

#define T_STEPS 512
#define BS      256
#define IC      128
#define HC      256
#define G4      1024   // 4*HC
#define NB      128    // persistent CTAs = 8 m-tiles x 16 n-groups (1/SM, co-resident)
#define NT      256    // threads per persistent CTA (2 warps per SMSP)

// ---------------- scratch (static device globals; no runtime allocation) ----------------
__device__ float g_gin [(size_t)T_STEPS * BS * G4];  // per-layer input projections (+biases)
__device__ float g_seq0[(size_t)T_STEPS * BS * HC];  // layer-0 output sequence
__device__ float g_h  [2][BS * HC];                  // h double-buffered by step parity
__device__ float g_ncb[2][BS * HC];                  // nc (for du dot) double-buffered
__device__ float g_du[BS];                           // carried across layers
__device__ int   g_skip[BS];                         // carried across layers
__device__ unsigned g_count;                         // grid barrier counter (monotonic)

// ---------------------------------------------------------------------------------------
// XLA-exact elementwise math (EmitFastTanh + LogisticExpander).
// ---------------------------------------------------------------------------------------
__device__ __forceinline__ float tanh_xla(float x)
{
    float ax = fabsf(x);
    float xc = fmaxf(-9.0f, fminf(x, 9.0f));
    float x2 = __fmul_rn(xc, xc);
    float p = -2.76076847742355e-16f;
    p = __fadd_rn(__fmul_rn(p, x2),  2.00018790482477e-13f);
    p = __fadd_rn(__fmul_rn(p, x2), -8.60467152213735e-11f);
    p = __fadd_rn(__fmul_rn(p, x2),  5.12229709037114e-08f);
    p = __fadd_rn(__fmul_rn(p, x2),  1.48572235717979e-05f);
    p = __fadd_rn(__fmul_rn(p, x2),  6.37261928875436e-04f);
    p = __fadd_rn(__fmul_rn(p, x2),  4.89352455891786e-03f);
    p = __fmul_rn(p, xc);
    float q =  1.19825839466702e-06f;
    q = __fadd_rn(__fmul_rn(q, x2),  1.18534705686654e-04f);
    q = __fadd_rn(__fmul_rn(q, x2),  2.26843463243900e-03f);
    q = __fadd_rn(__fmul_rn(q, x2),  4.89352518554385e-03f);
    float r = __fdiv_rn(p, q);
    return (ax < 0.0004f) ? x : r;
}

__device__ __forceinline__ float logi_xla(float x)
{
    float t = tanh_xla(__fmul_rn(0.5f, x));
    return __fadd_rn(0.5f, __fmul_rn(0.5f, t));
}

// Monotonic-counter grid barrier — proven formulation (volatile poll), with a short
// tight-spin phase before nanosleep backoff to cut wakeup latency.
__device__ __forceinline__ void grid_sync(unsigned& nbar)
{
    __syncthreads();
    if (threadIdx.x == 0) {
        __threadfence();
        nbar += 1;
        const unsigned target = nbar * NB;
        atomicAdd(&g_count, 1u);
        int s = 0;
        while (*(volatile unsigned*)&g_count < target) {
            if (++s > 64) __nanosleep(64);
        }
    }
    __syncthreads();
}

// ---------------------------------------------------------------------------------------
// Input projection (unchanged — passed). Ascending-k single-accumulator FMA chains.
// ---------------------------------------------------------------------------------------
__global__ __launch_bounds__(256) void inproj_kernel(
    const float* __restrict__ xin, int useSeq0, int K,
    const float* __restrict__ Wih,
    const float* __restrict__ b0, const float* __restrict__ b1)
{
    const float* A = useSeq0 ? g_seq0 : xin;
    __shared__ float As[8][132];
    __shared__ float Bs[8][132];

    const int tid = threadIdx.x;
    const int n0  = blockIdx.x << 7;
    const int m0  = blockIdx.y << 7;
    const int ty  = tid >> 4;
    const int tx  = tid & 15;
    const int r   = tid >> 1;
    const int kc  = (tid & 1) << 2;

    const float* Ap = A   + (size_t)(m0 + r) * K + kc;
    const float* Wp = Wih + (size_t)(n0 + r) * K + kc;

    float acc[8][8] = {};
    const int nch = K >> 3;
    float4 pa = __ldg((const float4*)Ap);
    float4 pw = __ldg((const float4*)Wp);

    for (int ch = 0; ch < nch; ch++) {
        As[kc + 0][r] = pa.x; As[kc + 1][r] = pa.y; As[kc + 2][r] = pa.z; As[kc + 3][r] = pa.w;
        Bs[kc + 0][r] = pw.x; Bs[kc + 1][r] = pw.y; Bs[kc + 2][r] = pw.z; Bs[kc + 3][r] = pw.w;
        __syncthreads();
        if (ch + 1 < nch) {
            pa = __ldg((const float4*)(Ap + (ch + 1) * 8));
            pw = __ldg((const float4*)(Wp + (ch + 1) * 8));
        }
#pragma unroll
        for (int k = 0; k < 8; k++) {
            float4 a0 = *(const float4*)&As[k][ty << 3];
            float4 a1 = *(const float4*)&As[k][(ty << 3) + 4];
            float4 w0 = *(const float4*)&Bs[k][tx << 3];
            float4 w1 = *(const float4*)&Bs[k][(tx << 3) + 4];
            float ar[8] = {a0.x, a0.y, a0.z, a0.w, a1.x, a1.y, a1.z, a1.w};
            float br[8] = {w0.x, w0.y, w0.z, w0.w, w1.x, w1.y, w1.z, w1.w};
#pragma unroll
            for (int i = 0; i < 8; i++)
#pragma unroll
                for (int j = 0; j < 8; j++)
                    acc[i][j] = fmaf(ar[i], br[j], acc[i][j]);
        }
        __syncthreads();
    }

    const int col = n0 + (tx << 3);
    float bias[8];
#pragma unroll
    for (int j = 0; j < 8; j++) bias[j] = __fadd_rn(b0[col + j], b1[col + j]);
#pragma unroll
    for (int i = 0; i < 8; i++) {
        size_t row = (size_t)m0 + (ty << 3) + i;
        float* o = g_gin + row * G4 + col;
#pragma unroll
        for (int j = 0; j < 8; j++) o[j] = __fadd_rn(acc[i][j], bias[j]);
    }
}

// ---------------------------------------------------------------------------------------
// du-dot + state update (warps 0-3 only; 4 threads/row, exact Eigen 4-chain order).
// ---------------------------------------------------------------------------------------
__device__ __forceinline__ void dot_update(
    int parity, int m0, int b, int q4, const float* slw, float lb0v,
    float* su, float* sdu, int* sskip)
{
    const float* nrow = g_ncb[parity] + (size_t)(m0 + b) * HC;
    float a = 0.0f;
    for (int k = q4; k < HC; k += 4)
        a = fmaf(__ldcg(nrow + k), slw[k], a);
    float v1  = __fadd_rn(a,  __shfl_xor_sync(0xffffffffu, a, 1));
    float dot = __fadd_rn(v1, __shfl_xor_sync(0xffffffffu, v1, 2));
    if (q4 == 0) {
        const float uo  = su[b];
        const float duo = sdu[b];
        const int   m   = sskip[b];
        const float bu  = rintf(uo);                       // jnp.round (half-to-even)
        const float omb = __fsub_rn(1.0f, bu);
        float nu, ndu;
        if (!m) {
            float dn = logi_xla(__fadd_rn(dot, lb0v));
            nu = __fmul_rn(dn, bu); ndu = dn;
        } else {
            nu = __fmul_rn(fminf(fmaxf(__fadd_rn(uo, duo), 0.0f), 1.0f), omb);
            ndu = duo;
        }
        su[b] = nu; sdu[b] = ndu;
        sskip[b] = ((__fsub_rn(ceilf(__fdiv_rn(0.5f, nu)), 1.0f)) > 0.0f) ? 1 : 0;
    }
}

// ---------------------------------------------------------------------------------------
// Fused persistent per-layer kernel, NT=256 (2 warps/SMSP for latency hiding).
// CTA = (m-tile of 32 rows) x (n-group of 16 h-cols, all 4 gates). Thread tile 2x4.
// ---------------------------------------------------------------------------------------
#define WS_ELEMS (256 * 68)
#define HS_ELEMS (256 * 36)
#define DYN_SMEM ((WS_ELEMS + HS_ELEMS) * 4)

__global__ __launch_bounds__(NT, 1) void layer_kernel(
    const float* __restrict__ W,                   // Whh [1024][256]
    const float* __restrict__ lw, const float* __restrict__ lb,
    float* __restrict__ seq_out, int to_seq0,
    float* __restrict__ outH, float* __restrict__ outC)
{
    extern __shared__ float sm[];
    float* Ws = sm;               // [k][64 local gate-cols] pad 68
    float* Hs = sm + WS_ELEMS;    // [k][32 rows] pad 36
    __shared__ float sgates[32 * 68];
    __shared__ float cloc[32 * 16];
    __shared__ float hloc[32 * 16];
    __shared__ float slw[256];
    __shared__ float su[32], sdu[32];
    __shared__ int   sskip[32];

    const int tid   = threadIdx.x;
    const int bid   = blockIdx.x;
    const int ng    = bid & 15;          // n-group: h-cols [16ng, 16ng+16)
    const int m0    = (bid >> 4) * 32;   // m-tile rows
    const int jbase = ng << 4;
    const int tx    = tid & 15;          // GEMM: 4 local gate-cols (tx*4..+3)
    const int ty    = tid >> 4;          // GEMM: 2 rows (2ty, 2ty+1)
    const int wid   = tid >> 5;
    const int lane  = tid & 31;
    const int pr    = tid >> 3;          // pointwise row 0..31
    const int pc    = (tid & 7) << 1;    // pointwise 2 cols (pc, pc+1) of 16

    // lw + Whh slab (64 gate-cols x 256 k) cached in SMEM, transposed to [k][c]
    slw[tid] = lw[tid];
    const float lb0v = lb[0];
    for (int i = tid; i < 64 * 64; i += NT) {
        int c  = i >> 6;                              // local gate-col 0..63
        int k4 = (i & 63) << 2;
        int grow = (c >> 4) * HC + jbase + (c & 15);  // Whh row (global gate col)
        float4 v = __ldcg((const float4*)(W + (size_t)grow * HC + k4));
        Ws[(k4 + 0) * 68 + c] = v.x; Ws[(k4 + 1) * 68 + c] = v.y;
        Ws[(k4 + 2) * 68 + c] = v.z; Ws[(k4 + 3) * 68 + c] = v.w;
    }

    if (tid < 32) {
        su[tid]    = 1.0f;
        sdu[tid]   = g_du[m0 + tid];
        sskip[tid] = g_skip[m0 + tid];
    }
    for (int i = tid; i < 32 * 16; i += NT) { cloc[i] = 0.0f; hloc[i] = 0.0f; }
    __syncthreads();

    unsigned nbar = 0;

    for (int t = 0; t < T_STEPS; t++) {
        // gin prefetch: this thread's 2x4 gate patch (static data)
        float4 pg[2];
        {
            const int gate = tx >> 2;
            const int gj0  = (tx & 3) << 2;
            const float* gp = g_gin + ((size_t)t * BS + m0 + (ty << 1)) * G4
                              + gate * HC + jbase + gj0;
            pg[0] = __ldcg((const float4*)gp);
            pg[1] = __ldcg((const float4*)(gp + G4));
        }

        // Hs load: h(t) from parity buffer t&1 -> [k][m]
        {
            const float* hsrc = g_h[t & 1];
            for (int i = tid; i < 32 * 64; i += NT) {
                int rr = i >> 6;
                int k4 = (i & 63) << 2;
                float4 v = __ldcg((const float4*)(hsrc + (size_t)(m0 + rr) * HC + k4));
                Hs[(k4 + 0) * 36 + rr] = v.x; Hs[(k4 + 1) * 36 + rr] = v.y;
                Hs[(k4 + 2) * 36 + rr] = v.z; Hs[(k4 + 3) * 36 + rr] = v.w;
            }
        }

        // state update from previous step's nc (warps 0-3)
        if (t > 0 && tid < 128) dot_update((t - 1) & 1, m0, tid >> 2, tid & 3,
                                           slw, lb0v, su, sdu, sskip);
        __syncthreads();

        // GEMM: 32 rows x 64 local gate-cols -> sgates (+gin). Warp rows: 4*wid..+3.
        {
            int fl = (lane < 4) ? sskip[(wid << 2) + lane] : 1;
            const bool allskip = __all_sync(0xffffffffu, fl != 0);
            if (!allskip) {
                float acc[2][4] = {};
                const float* hp = &Hs[ty << 1];
                const float* wp = &Ws[tx << 2];
#pragma unroll 8
                for (int k = 0; k < HC; k++) {       // strictly ascending k
                    float2 a = *(const float2*)(hp + k * 36);
                    float4 b = *(const float4*)(wp + k * 68);
                    acc[0][0] = fmaf(a.x, b.x, acc[0][0]); acc[0][1] = fmaf(a.x, b.y, acc[0][1]);
                    acc[0][2] = fmaf(a.x, b.z, acc[0][2]); acc[0][3] = fmaf(a.x, b.w, acc[0][3]);
                    acc[1][0] = fmaf(a.y, b.x, acc[1][0]); acc[1][1] = fmaf(a.y, b.y, acc[1][1]);
                    acc[1][2] = fmaf(a.y, b.z, acc[1][2]); acc[1][3] = fmaf(a.y, b.w, acc[1][3]);
                }
#pragma unroll
                for (int i = 0; i < 2; i++) {
                    float4 v = make_float4(__fadd_rn(acc[i][0], pg[i].x),
                                           __fadd_rn(acc[i][1], pg[i].y),
                                           __fadd_rn(acc[i][2], pg[i].z),
                                           __fadd_rn(acc[i][3], pg[i].w));
                    *(float4*)&sgates[((ty << 1) + i) * 68 + (tx << 2)] = v;
                }
            }
        }
        __syncthreads();

        // pointwise: 1 row x 2 cols per thread, all CTA-local
        {
            const float uo  = su[pr];
            const int   m   = sskip[pr];
            const float bu  = rintf(uo);
            const float omb = __fsub_rn(1.0f, bu);
            float* cl = cloc + pr * 16 + pc;
            float* hl = hloc + pr * 16 + pc;
            float nh[2], nc[2];
            if (!m) {
                const float* sg = sgates + pr * 68;
#pragma unroll
                for (int s = 0; s < 2; s++) {
                    int jl = pc + s;
                    float gi = sg[jl], gf = sg[16 + jl], gg = sg[32 + jl], go = sg[48 + jl];
                    float cc = __fadd_rn(__fmul_rn(logi_xla(gf), cl[s]),
                                         __fmul_rn(logi_xla(gi), tanh_xla(gg)));
                    float ch = __fmul_rn(logi_xla(go), tanh_xla(cc));
                    nc[s] = __fmul_rn(cc, bu);
                    nh[s] = __fmul_rn(ch, bu);
                }
            } else {
#pragma unroll
                for (int s = 0; s < 2; s++) {
                    nh[s] = __fmul_rn(hl[s], omb);
                    nc[s] = __fmul_rn(cl[s], omb);
                }
            }
            cl[0] = nc[0]; cl[1] = nc[1];
            hl[0] = nh[0]; hl[1] = nh[1];

            const size_t roff = (size_t)(m0 + pr) * HC + jbase + pc;
            float2 nh2 = make_float2(nh[0], nh[1]);
            __stcg((float2*)(g_h[(t + 1) & 1] + roff), nh2);      // next-step h buffer
            if (!m) {
                __stcg((float2*)(g_ncb[t & 1] + roff), make_float2(nc[0], nc[1]));
            }
            float* dp = (to_seq0 ? g_seq0 : seq_out) + (size_t)t * BS * HC + roff;
            __stcg((float2*)dp, nh2);
        }

        grid_sync(nbar);
    }

    // final state update -> carried du/skip + h/c outputs
    if (tid < 128) dot_update((T_STEPS - 1) & 1, m0, tid >> 2, tid & 3,
                              slw, lb0v, su, sdu, sskip);
    __syncthreads();
    if (ng == 0 && tid < 32) {
        g_du[m0 + tid]   = sdu[tid];
        g_skip[m0 + tid] = sskip[tid];
    }
    {
        const size_t roff = (size_t)(m0 + pr) * HC + jbase + pc;
        *(float2*)(outH + roff) = *(float2*)(hloc + pr * 16 + pc);
        *(float2*)(outC + roff) = *(float2*)(cloc + pr * 16 + pc);
    }
}

// ---------------------------------------------------------------------------------------
__global__ void init0_kernel()   // before layer 0: full reset
{
    int i = blockIdx.x * blockDim.x + threadIdx.x;
    if (i < BS * HC) g_h[0][i] = 0.0f;
    if (i < BS)      { g_du[i] = 0.0f; g_skip[i] = 0; }
    if (i == 0)      g_count = 0u;
}

__global__ void init1_kernel()   // before layer 1: keep carried du/skip
{
    int i = blockIdx.x * blockDim.x + threadIdx.x;
    if (i < BS * HC) g_h[0][i] = 0.0f;
    if (i == 0)      g_count = 0u;
}

// ---------------------------------------------------------------------------------------
extern "C" void kernel_launch(void* const* d_in, const int* in_sizes, int n_in,
                              void* d_out, int out_size)
{
    const float* x    = (const float*)d_in[0];
    const float* Wih0 = (const float*)d_in[1];
    const float* Whh0 = (const float*)d_in[2];
    const float* bih0 = (const float*)d_in[3];
    const float* bhh0 = (const float*)d_in[4];
    const float* lw0  = (const float*)d_in[5];
    const float* lb0  = (const float*)d_in[6];
    const float* Wih1 = (const float*)d_in[7];
    const float* Whh1 = (const float*)d_in[8];
    const float* bih1 = (const float*)d_in[9];
    const float* bhh1 = (const float*)d_in[10];
    const float* lw1  = (const float*)d_in[11];
    const float* lb1  = (const float*)d_in[12];

    float* out   = (float*)d_out;                         // [T, BS, HC]
    float* outHs = out + (size_t)T_STEPS * BS * HC;       // [2, BS, HC]
    float* outCs = outHs + 2 * BS * HC;                   // [2, BS, HC]

    cudaFuncSetAttribute(layer_kernel, cudaFuncAttributeMaxDynamicSharedMemorySize, DYN_SMEM);

    dim3 proj_grid(G4 / 128, (T_STEPS * BS) / 128);       // (8, 1024)

    // launch order keeps layer_kernel as launch #6 (ncu -s 5 -c 1 captures it)
    inproj_kernel<<<proj_grid, 256>>>(x, 0, IC, Wih0, bih0, bhh0);          // 1
    init0_kernel<<<256, 256>>>();                                           // 2
    layer_kernel<<<NB, NT, DYN_SMEM>>>(Whh0, lw0, lb0, nullptr, 1,          // 3
                                       outHs, outCs);
    inproj_kernel<<<proj_grid, 256>>>(nullptr, 1, HC, Wih1, bih1, bhh1);    // 4
    init1_kernel<<<256, 256>>>();                                           // 5
    layer_kernel<<<NB, NT, DYN_SMEM>>>(Whh1, lw1, lb1, out, 0,              // 6
                                       outHs + BS * HC, outCs + BS * HC);
}